// round 13
// baseline (speedup 1.0000x reference)
#include <cuda_runtime.h>
#include <cuda_bf16.h>
#include <math.h>

#define SS     16      // samples per group
#define CC     128     // channels
#define GNN    256     // groups per batch item
#define NR     9       // max instance rows (bg + 8 fg labels)
#define MAXG   32768
#define GP     2       // groups per CTA
#define CPAD   129     // padded channel pitch in staged smem
#define MPITCH 132     // padded pitch of mean rows (528 B: bank-staggered, 16B-mult)
#define NTHR   256

// per-CTA packed partials: (sum gl*gv, sum gv) — deterministic scratch
__device__ __align__(16) float2 g_part[MAXG / GP];

__global__ void __launch_bounds__(NTHR) proposal_clloss_group_kernel(
    const int*   __restrict__ labs,    // [G*S]
    const float* __restrict__ feats,   // [bs, C, Gn, S]
    const int*   __restrict__ idxs,    // [G*S]
    const float* __restrict__ ctx)     // [C]
{
    __shared__ float s_sf[GP * SS * CPAD];               // staged [gs][s][c]
    __shared__ __align__(16) float s_M[GP * NR * MPITCH];
    __shared__ float s_sim[GP][NR * NR];
    __shared__ int   s_order[GP][SS];                    // samples sorted by row
    __shared__ int   s_start[GP][NR];
    __shared__ int   s_end[GP][NR];
    __shared__ float s_inv[GP][NR];
    __shared__ int   s_instnum[GP];
    __shared__ int   s_hasbg[GP];
    __shared__ float s_res[GP];
    __shared__ float s_gv[GP];

    const int tid   = threadIdx.x;
    const int warp  = tid >> 5;
    const int lane  = tid & 31;
    const int gbase = blockIdx.x * GP;

    // ----- issue coalesced feature loads early --------------------------
    const int    g_in = gbase % GNN;
    const size_t base = (size_t)(gbase - g_in) * (CC * SS) + (size_t)g_in * SS;

    float4 v[4];
    int    dst_c[4], dst_r[4];
    #pragma unroll
    for (int it = 0; it < 4; it++) {
        const int flat = it * NTHR + tid;
        const int c  = flat >> 3;
        const int r  = flat & 7;        // gs*4 + q
        dst_c[it] = c;
        dst_r[it] = r;
        const float* p = feats + base + (size_t)c * (GNN * SS)
                       + (r >> 2) * SS + (r & 3) * 4;
        v[it] = *reinterpret_cast<const float4*>(p);
    }
    const float ctx_c = __ldg(ctx + (tid & (CC - 1)));

    // ----- Phase A: per-group metadata, warp w handles group w ----------
    if (warp < GP) {
        const int g   = gbase + warp;
        const bool smp = (lane < SS);
        const int idx_v = smp ? idxs[g * SS + lane] : (0x40000000 + lane);
        const int lab_v = smp ? labs[g * SS + lane] : 0;

        const unsigned m_idx = __match_any_sync(0xffffffffu, idx_v);
        const bool first = ((m_idx & ((1u << lane) - 1u)) == 0u);
        const int u = __popc(__ballot_sync(0xffffffffu, first && smp));

        const bool valid  = smp && (lane < u);
        const int labcode = valid ? (lab_v + 1) : 31;   // 0..8 valid, 31 = none

        unsigned b[NR];
        int cnt[NR];
        #pragma unroll
        for (int vv = 0; vv < NR; vv++) {
            b[vv]   = __ballot_sync(0xffffffffu, labcode == vv);
            cnt[vv] = __popc(b[vv]);
        }
        unsigned pres = 0;
        #pragma unroll
        for (int vv = 0; vv < NR; vv++) pres |= (cnt[vv] ? 1u : 0u) << vv;
        int pr[NR + 1];
        pr[0] = 0;
        #pragma unroll
        for (int vv = 0; vv < NR; vv++) pr[vv + 1] = pr[vv] + cnt[vv];

        const int hasbg   = (int)(pres & 1u);
        const int instnum = __popc(pres >> 1) + 1;

        if (valid) {
            const int pos = pr[labcode] + __popc(b[labcode] & ((1u << lane) - 1u));
            s_order[warp][pos] = lane;
        }
        if (lane < NR) {
            s_start[warp][lane] = 0;
            s_end[warp][lane]   = 0;
            s_inv[warp][lane]   = 1.0f;
        }
        __syncwarp();
        if (lane < NR && cnt[lane] > 0) {
            const int r = (lane == 0) ? 0
                        : 1 + __popc((pres & ((1u << lane) - 1u)) >> 1);
            s_start[warp][r] = pr[lane];
            s_end[warp][r]   = pr[lane] + cnt[lane];
            s_inv[warp][r]   = 1.0f / (float)cnt[lane];
        }
        if (lane == 0) { s_instnum[warp] = instnum; s_hasbg[warp] = hasbg; }
    }

    // ----- stage features to smem (transposed [gs][s][c]) ----------------
    #pragma unroll
    for (int it = 0; it < 4; it++) {
        const int c  = dst_c[it];
        const int gs = dst_r[it] >> 2;
        const int q  = dst_r[it] & 3;
        float* d = s_sf + (gs * SS + q * 4) * CPAD + c;
        d[0 * CPAD] = v[it].x;
        d[1 * CPAD] = v[it].y;
        d[2 * CPAD] = v[it].z;
        d[3 * CPAD] = v[it].w;
    }
    __syncthreads();

    // ----- Phase B: per-channel instance means (segment gather) ----------
    {
        const int gs   = tid >> 7;        // 0..1
        const int c    = tid & (CC - 1);  // 0..127
        const int inum = s_instnum[gs];
        const float* fcol = s_sf + gs * SS * CPAD + c;
        float* mrow = s_M + gs * NR * MPITCH + c;
        for (int r = 0; r < inum; r++) {
            const int st = s_start[gs][r];
            const int en = s_end[gs][r];
            float x = 0.0f;
            for (int k = st; k < en; k++)
                x += fcol[s_order[gs][k] * CPAD];
            mrow[r * MPITCH] = x * s_inv[gs][r];
        }
        if (!s_hasbg[gs])
            mrow[0] = ctx_c;               // row 0 = context compensation
    }
    __syncthreads();

    // ----- Phase C: sim = (M M^T)/T — 2 lanes per pair, single pass ------
    {
        const int slot = tid >> 1;         // 0..127
        const int half = tid & 1;
        const int gs   = slot >> 6;        // 0..1
        const int p    = slot & 63;
        const int inum = s_instnum[gs];
        const int P    = inum * (inum + 1) / 2;   // <= 45
        const int pp   = (p < P) ? p : 0;

        int i = (int)((sqrtf(8.0f * (float)pp + 1.0f) - 1.0f) * 0.5f);
        if (i * (i + 1) / 2 > pp) i--;
        if ((i + 1) * (i + 2) / 2 <= pp) i++;
        const int j = pp - i * (i + 1) / 2;

        const float4* ra = reinterpret_cast<const float4*>(
                               s_M + (gs * NR + i) * MPITCH);
        const float4* rb = reinterpret_cast<const float4*>(
                               s_M + (gs * NR + j) * MPITCH);
        float a0 = 0.f, a1 = 0.f, a2 = 0.f, a3 = 0.f;
        #pragma unroll
        for (int k = 0; k < 16; k += 4) {
            const float4 xa0 = ra[2 * (k + 0) + half], xb0 = rb[2 * (k + 0) + half];
            const float4 xa1 = ra[2 * (k + 1) + half], xb1 = rb[2 * (k + 1) + half];
            const float4 xa2 = ra[2 * (k + 2) + half], xb2 = rb[2 * (k + 2) + half];
            const float4 xa3 = ra[2 * (k + 3) + half], xb3 = rb[2 * (k + 3) + half];
            a0 += xa0.x * xb0.x + xa0.y * xb0.y + xa0.z * xb0.z + xa0.w * xb0.w;
            a1 += xa1.x * xb1.x + xa1.y * xb1.y + xa1.z * xb1.z + xa1.w * xb1.w;
            a2 += xa2.x * xb2.x + xa2.y * xb2.y + xa2.z * xb2.z + xa2.w * xb2.w;
            a3 += xa3.x * xb3.x + xa3.y * xb3.y + xa3.z * xb3.z + xa3.w * xb3.w;
        }
        float pa = (a0 + a1) + (a2 + a3);
        pa += __shfl_xor_sync(0xffffffffu, pa, 1);
        if (half == 0 && p < P) {
            const float x = pa * 5.0f;     // 1/T, T = 0.2
            s_sim[gs][i * NR + j] = x;
            s_sim[gs][j * NR + i] = x;
        }
    }
    __syncthreads();

    // ----- Phase D: per-row logsumexp, group loss ------------------------
    if (warp < GP) {
        const int gs   = warp;
        const int inum = s_instnum[gs];
        float li = 0.0f;
        const int i = lane + 1;
        if (i < inum) {
            float mx = -3.402823466e38f;
            for (int j = 0; j < inum; j++)
                mx = fmaxf(mx, s_sim[gs][i * NR + j]);
            float sum = 0.0f;
            for (int j = 0; j < inum; j++)
                sum += __expf(s_sim[gs][i * NR + j] - mx);
            li = mx + __logf(sum) - s_sim[gs][i * NR + i];
        }
        #pragma unroll
        for (int o = 16; o; o >>= 1)
            li += __shfl_xor_sync(0xffffffffu, li, o);
        if (lane == 0) {
            const float gv = (inum >= 2) ? 1.0f : 0.0f;
            s_res[gs] = (inum >= 2) ? (li / (float)(inum - 1)) * gv : 0.0f;
            s_gv[gs]  = gv;
        }
    }
    __syncthreads();

    if (tid == 0)
        g_part[blockIdx.x] = make_float2(s_res[0] + s_res[1],
                                         s_gv[0] + s_gv[1]);
}

__global__ void __launch_bounds__(1024) proposal_clloss_reduce_kernel(
    float* __restrict__ out, int nCTA)
{
    __shared__ float sn[32];
    __shared__ float sd[32];
    const int tid  = threadIdx.x;
    const int warp = tid >> 5;
    const int lane = tid & 31;

    const float4* p4 = reinterpret_cast<const float4*>(g_part);
    const int nq = nCTA >> 1;              // float4 count (nCTA even)
    float n = 0.0f, d = 0.0f;
    #pragma unroll 2
    for (int i = tid; i < nq; i += 1024) {
        const float4 x = p4[i];            // (gl0, gv0, gl1, gv1)
        n += x.x + x.z;
        d += x.y + x.w;
    }
    #pragma unroll
    for (int o = 16; o; o >>= 1) {
        n += __shfl_xor_sync(0xffffffffu, n, o);
        d += __shfl_xor_sync(0xffffffffu, d, o);
    }
    if (lane == 0) { sn[warp] = n; sd[warp] = d; }
    __syncthreads();
    if (warp == 0) {
        float nn = sn[lane];
        float dd = sd[lane];
        #pragma unroll
        for (int o = 16; o; o >>= 1) {
            nn += __shfl_xor_sync(0xffffffffu, nn, o);
            dd += __shfl_xor_sync(0xffffffffu, dd, o);
        }
        if (lane == 0) out[0] = nn / dd * 0.1f;
    }
}

extern "C" void kernel_launch(void* const* d_in, const int* in_sizes, int n_in,
                              void* d_out, int out_size)
{
    const int*   labs  = (const int*)  d_in[0];  // proposal_instance_mask [bs,Gn,S]
    const float* feats = (const float*)d_in[1];  // grouped_features [bs,C,Gn,S]
    const int*   idxs  = (const int*)  d_in[2];  // grouped_indices [bs,Gn,S]
    const float* ctx   = (const float*)d_in[3];  // context_compen [1,C]
    float*       out   = (float*)d_out;

    const int G = in_sizes[0] / SS;              // total group count (8192)
    const int nCTA = G / GP;

    proposal_clloss_group_kernel<<<nCTA, NTHR>>>(labs, feats, idxs, ctx);
    proposal_clloss_reduce_kernel<<<1, 1024>>>(out, nCTA);
}

// round 15
// speedup vs baseline: 1.7214x; 1.7214x over previous
#include <cuda_runtime.h>
#include <cuda_bf16.h>
#include <math.h>

#define SS     16      // samples per group
#define CC     128     // channels
#define GNN    256     // groups per batch item
#define NR     9       // max instance rows (bg + 8 fg labels)
#define MAXG   32768
#define GP     2       // groups per CTA
#define CPAD   129     // padded channel pitch in staged smem
#define NTHR   256

// per-CTA packed partials: (sum gl*gv, sum gv) — deterministic scratch
__device__ __align__(16) float2 g_part[MAXG / GP];

// triangle pair LUT: p -> (i, j), j <= i, p = i(i+1)/2 + j, for instnum <= 9
__device__ __constant__ signed char TRI_I[48] = {
    0, 1,1, 2,2,2, 3,3,3,3, 4,4,4,4,4, 5,5,5,5,5,5,
    6,6,6,6,6,6,6, 7,7,7,7,7,7,7,7, 8,8,8,8,8,8,8,8,8, 0,0,0 };
__device__ __constant__ signed char TRI_J[48] = {
    0, 0,1, 0,1,2, 0,1,2,3, 0,1,2,3,4, 0,1,2,3,4,5,
    0,1,2,3,4,5,6, 0,1,2,3,4,5,6,7, 0,1,2,3,4,5,6,7,8, 0,0,0 };

__global__ void __launch_bounds__(NTHR) proposal_clloss_group_kernel(
    const int*   __restrict__ labs,    // [G*S]
    const float* __restrict__ feats,   // [bs, C, Gn, S]
    const int*   __restrict__ idxs,    // [G*S]
    const float* __restrict__ ctx)     // [C]
{
    __shared__ float s_sf[GP * SS * CPAD];               // staged [gs][s][c]
    __shared__ __align__(16) float s_M[GP][NR][CC];      // instance-mean rows
    __shared__ float s_sim[GP][NR * NR];
    __shared__ int   s_order[GP][SS];                    // samples sorted by row
    __shared__ int   s_start[GP][NR];
    __shared__ int   s_end[GP][NR];
    __shared__ float s_inv[GP][NR];
    __shared__ int   s_instnum[GP];
    __shared__ int   s_hasbg[GP];
    __shared__ float s_res[GP];
    __shared__ float s_gv[GP];

    const int tid   = threadIdx.x;
    const int warp  = tid >> 5;
    const int lane  = tid & 31;
    const int gbase = blockIdx.x * GP;

    // ----- issue coalesced feature loads early --------------------------
    // 2 adjacent groups: per channel c, GP*SS floats = 128 B contiguous,
    // 128-B aligned (g_in even). flat = c*8 + gs*4 + q; 1024 float4 total.
    const int    g_in = gbase % GNN;
    const size_t base = (size_t)(gbase - g_in) * (CC * SS) + (size_t)g_in * SS;

    float4 v[4];
    int    dst_c[4], dst_r[4];
    #pragma unroll
    for (int it = 0; it < 4; it++) {
        const int flat = it * NTHR + tid;
        const int c  = flat >> 3;
        const int r  = flat & 7;        // gs*4 + q
        dst_c[it] = c;
        dst_r[it] = r;
        const float* p = feats + base + (size_t)c * (GNN * SS)
                       + (r >> 2) * SS + (r & 3) * 4;
        v[it] = *reinterpret_cast<const float4*>(p);
    }
    const float ctx_c = __ldg(ctx + (tid & (CC - 1)));

    // ----- Phase A: per-group metadata, warp w handles group w ----------
    if (warp < GP) {
        const int g   = gbase + warp;
        const bool smp = (lane < SS);
        const int idx_v = smp ? idxs[g * SS + lane] : (0x40000000 + lane);
        const int lab_v = smp ? labs[g * SS + lane] : 0;

        const unsigned m_idx = __match_any_sync(0xffffffffu, idx_v);
        const bool first = ((m_idx & ((1u << lane) - 1u)) == 0u);
        const int u = __popc(__ballot_sync(0xffffffffu, first && smp));

        const bool valid  = smp && (lane < u);
        const int labcode = valid ? (lab_v + 1) : 31;   // 0..8 valid, 31 = none

        unsigned b[NR];
        int cnt[NR];
        #pragma unroll
        for (int vv = 0; vv < NR; vv++) {
            b[vv]   = __ballot_sync(0xffffffffu, labcode == vv);
            cnt[vv] = __popc(b[vv]);
        }
        unsigned pres = 0;
        #pragma unroll
        for (int vv = 0; vv < NR; vv++) pres |= (cnt[vv] ? 1u : 0u) << vv;
        int pr[NR + 1];
        pr[0] = 0;
        #pragma unroll
        for (int vv = 0; vv < NR; vv++) pr[vv + 1] = pr[vv] + cnt[vv];

        const int hasbg   = (int)(pres & 1u);
        const int instnum = __popc(pres >> 1) + 1;

        if (valid) {
            const int pos = pr[labcode] + __popc(b[labcode] & ((1u << lane) - 1u));
            s_order[warp][pos] = lane;
        }
        if (lane < NR) {
            s_start[warp][lane] = 0;
            s_end[warp][lane]   = 0;
            s_inv[warp][lane]   = 1.0f;
        }
        __syncwarp();
        if (lane < NR && cnt[lane] > 0) {
            const int r = (lane == 0) ? 0
                        : 1 + __popc((pres & ((1u << lane) - 1u)) >> 1);
            s_start[warp][r] = pr[lane];
            s_end[warp][r]   = pr[lane] + cnt[lane];
            s_inv[warp][r]   = 1.0f / (float)cnt[lane];
        }
        if (lane == 0) { s_instnum[warp] = instnum; s_hasbg[warp] = hasbg; }
    }

    // ----- stage features to smem (transposed [gs][s][c]) ----------------
    #pragma unroll
    for (int it = 0; it < 4; it++) {
        const int c  = dst_c[it];
        const int gs = dst_r[it] >> 2;
        const int q  = dst_r[it] & 3;
        float* d = s_sf + (gs * SS + q * 4) * CPAD + c;
        d[0 * CPAD] = v[it].x;
        d[1 * CPAD] = v[it].y;
        d[2 * CPAD] = v[it].z;
        d[3 * CPAD] = v[it].w;
    }
    __syncthreads();

    // ----- Phase B: per-channel instance means (segment gather) ----------
    {
        const int gs   = tid >> 7;        // 0..1
        const int c    = tid & (CC - 1);  // 0..127
        const int inum = s_instnum[gs];
        const float* fcol = s_sf + gs * SS * CPAD + c;
        for (int r = 0; r < inum; r++) {
            const int st = s_start[gs][r];
            const int en = s_end[gs][r];
            float x = 0.0f;
            for (int k = st; k < en; k++)
                x += fcol[s_order[gs][k] * CPAD];
            s_M[gs][r][c] = x * s_inv[gs][r];
        }
        if (!s_hasbg[gs])
            s_M[gs][0][c] = ctx_c;         // row 0 = context compensation
    }
    __syncthreads();

    // ----- Phase C: sim = (M M^T)/T — warp per pair, static unroll -------
    {
        const int gs   = warp & 1;
        const int sub  = warp >> 1;         // 0..3
        const int inum = s_instnum[gs];
        const int P = inum * (inum + 1) / 2;   // <= 45
        #pragma unroll
        for (int it = 0; it < 12; it++) {
            const int p   = sub + it * 4;
            const bool act = (p < P);
            const int pp  = act ? p : 0;
            const int i = TRI_I[pp];
            const int j = TRI_J[pp];
            const float4 a  = reinterpret_cast<const float4*>(s_M[gs][i])[lane];
            const float4 bb = reinterpret_cast<const float4*>(s_M[gs][j])[lane];
            float pa = a.x * bb.x + a.y * bb.y + a.z * bb.z + a.w * bb.w;
            #pragma unroll
            for (int o = 16; o; o >>= 1)
                pa += __shfl_xor_sync(0xffffffffu, pa, o);
            if (act && lane == 0) {
                const float x = pa * 5.0f;  // 1/T, T = 0.2
                s_sim[gs][i * NR + j] = x;
                s_sim[gs][j * NR + i] = x;
            }
        }
    }
    __syncthreads();

    // ----- Phase D: per-row logsumexp, group loss (static unroll) --------
    if (warp < GP) {
        const int gs   = warp;
        const int inum = s_instnum[gs];
        float li = 0.0f;
        const int i = lane + 1;
        if (i < inum) {
            float sv[NR];
            #pragma unroll
            for (int j = 0; j < NR; j++)
                sv[j] = (j < inum) ? s_sim[gs][i * NR + j] : -3.402823466e38f;
            float mx = sv[0];
            #pragma unroll
            for (int j = 1; j < NR; j++) mx = fmaxf(mx, sv[j]);
            float sum = 0.0f;
            #pragma unroll
            for (int j = 0; j < NR; j++)
                sum += (j < inum) ? __expf(sv[j] - mx) : 0.0f;
            li = mx + __logf(sum) - s_sim[gs][i * NR + i];
        }
        #pragma unroll
        for (int o = 16; o; o >>= 1)
            li += __shfl_xor_sync(0xffffffffu, li, o);
        if (lane == 0) {
            const float gv = (inum >= 2) ? 1.0f : 0.0f;
            s_res[gs] = (inum >= 2) ? (li / (float)(inum - 1)) : 0.0f;
            s_gv[gs]  = gv;
        }
    }
    __syncthreads();

    if (tid == 0)
        g_part[blockIdx.x] = make_float2(s_res[0] + s_res[1],
                                         s_gv[0] + s_gv[1]);
}

__global__ void __launch_bounds__(1024) proposal_clloss_reduce_kernel(
    float* __restrict__ out, int nCTA)
{
    __shared__ float sn[32];
    __shared__ float sd[32];
    const int tid  = threadIdx.x;
    const int warp = tid >> 5;
    const int lane = tid & 31;

    const float4* p4 = reinterpret_cast<const float4*>(g_part);
    const int nq = nCTA >> 1;              // float4 count (nCTA even)
    float n = 0.0f, d = 0.0f;
    #pragma unroll 2
    for (int i = tid; i < nq; i += 1024) {
        const float4 x = p4[i];            // (gl0, gv0, gl1, gv1)
        n += x.x + x.z;
        d += x.y + x.w;
    }
    #pragma unroll
    for (int o = 16; o; o >>= 1) {
        n += __shfl_xor_sync(0xffffffffu, n, o);
        d += __shfl_xor_sync(0xffffffffu, d, o);
    }
    if (lane == 0) { sn[warp] = n; sd[warp] = d; }
    __syncthreads();
    if (warp == 0) {
        float nn = sn[lane];
        float dd = sd[lane];
        #pragma unroll
        for (int o = 16; o; o >>= 1) {
            nn += __shfl_xor_sync(0xffffffffu, nn, o);
            dd += __shfl_xor_sync(0xffffffffu, dd, o);
        }
        if (lane == 0) out[0] = nn / dd * 0.1f;
    }
}

extern "C" void kernel_launch(void* const* d_in, const int* in_sizes, int n_in,
                              void* d_out, int out_size)
{
    const int*   labs  = (const int*)  d_in[0];  // proposal_instance_mask [bs,Gn,S]
    const float* feats = (const float*)d_in[1];  // grouped_features [bs,C,Gn,S]
    const int*   idxs  = (const int*)  d_in[2];  // grouped_indices [bs,Gn,S]
    const float* ctx   = (const float*)d_in[3];  // context_compen [1,C]
    float*       out   = (float*)d_out;

    const int G = in_sizes[0] / SS;              // total group count (8192)
    const int nCTA = G / GP;

    proposal_clloss_group_kernel<<<nCTA, NTHR>>>(labs, feats, idxs, ctx);
    proposal_clloss_reduce_kernel<<<1, 1024>>>(out, nCTA);
}

// round 16
// speedup vs baseline: 1.9493x; 1.1324x over previous
#include <cuda_runtime.h>
#include <cuda_bf16.h>
#include <math.h>

#define SS     16      // samples per group
#define CC     128     // channels
#define GNN    256     // groups per batch item
#define NR     9       // max instance rows (bg + 8 fg labels)
#define MAXG   32768
#define GP     2       // groups per CTA
#define CPAD   129     // padded channel pitch in staged smem
#define NTHR   256

// per-CTA packed partials: (sum gl*gv, sum gv) — deterministic scratch
__device__ __align__(16) float2 g_part[MAXG / GP];

// triangle pair LUT: p -> (i, j), j <= i, p = i(i+1)/2 + j, for instnum <= 9
__device__ __constant__ signed char TRI_I[45] = {
    0, 1,1, 2,2,2, 3,3,3,3, 4,4,4,4,4, 5,5,5,5,5,5,
    6,6,6,6,6,6,6, 7,7,7,7,7,7,7,7, 8,8,8,8,8,8,8,8,8 };
__device__ __constant__ signed char TRI_J[45] = {
    0, 0,1, 0,1,2, 0,1,2,3, 0,1,2,3,4, 0,1,2,3,4,5,
    0,1,2,3,4,5,6, 0,1,2,3,4,5,6,7, 0,1,2,3,4,5,6,7,8 };

__global__ void __launch_bounds__(NTHR, 7) proposal_clloss_group_kernel(
    const int*   __restrict__ labs,    // [G*S]
    const float* __restrict__ feats,   // [bs, C, Gn, S]
    const int*   __restrict__ idxs,    // [G*S]
    const float* __restrict__ ctx)     // [C]
{
    __shared__ float s_sf[GP * SS * CPAD];               // staged [gs][s][c]
    __shared__ __align__(16) float s_M[GP][NR][CC];      // instance-mean rows
    __shared__ float s_sim[GP][NR * NR];
    __shared__ unsigned s_olo[GP], s_ohi[GP];            // packed sample order
    __shared__ int   s_start[GP][NR];
    __shared__ int   s_end[GP][NR];
    __shared__ float s_inv[GP][NR];
    __shared__ int   s_instnum[GP];
    __shared__ int   s_hasbg[GP];
    __shared__ float s_res[GP];
    __shared__ float s_gv[GP];

    const int tid   = threadIdx.x;
    const int warp  = tid >> 5;
    const int lane  = tid & 31;
    const int gbase = blockIdx.x * GP;

    // ----- issue coalesced feature loads early --------------------------
    // 2 adjacent groups: per channel c, GP*SS floats = 128 B contiguous,
    // 128-B aligned (g_in even). flat = c*8 + gs*4 + q; 1024 float4 total.
    const int    g_in = gbase % GNN;
    const size_t base = (size_t)(gbase - g_in) * (CC * SS) + (size_t)g_in * SS;

    float4 v[4];
    int    dst_c[4], dst_r[4];
    #pragma unroll
    for (int it = 0; it < 4; it++) {
        const int flat = it * NTHR + tid;
        const int c  = flat >> 3;
        const int r  = flat & 7;        // gs*4 + q
        dst_c[it] = c;
        dst_r[it] = r;
        const float* p = feats + base + (size_t)c * (GNN * SS)
                       + (r >> 2) * SS + (r & 3) * 4;
        v[it] = *reinterpret_cast<const float4*>(p);
    }
    const float ctx_c = __ldg(ctx + (tid & (CC - 1)));

    // ----- Phase A: per-group metadata, warp w handles group w ----------
    if (warp < GP) {
        const int g   = gbase + warp;
        const bool smp = (lane < SS);
        const int idx_v = smp ? idxs[g * SS + lane] : (0x40000000 + lane);
        const int lab_v = smp ? labs[g * SS + lane] : 0;

        const unsigned m_idx = __match_any_sync(0xffffffffu, idx_v);
        const bool first = ((m_idx & ((1u << lane) - 1u)) == 0u);
        const int u = __popc(__ballot_sync(0xffffffffu, first && smp));

        const bool valid  = smp && (lane < u);
        const int labcode = valid ? (lab_v + 1) : 31;   // 0..8 valid, 31 = none

        unsigned b[NR];
        int cnt[NR];
        #pragma unroll
        for (int vv = 0; vv < NR; vv++) {
            b[vv]   = __ballot_sync(0xffffffffu, labcode == vv);
            cnt[vv] = __popc(b[vv]);
        }
        unsigned pres = 0;
        #pragma unroll
        for (int vv = 0; vv < NR; vv++) pres |= (cnt[vv] ? 1u : 0u) << vv;
        int pr[NR + 1];
        pr[0] = 0;
        #pragma unroll
        for (int vv = 0; vv < NR; vv++) pr[vv + 1] = pr[vv] + cnt[vv];

        const int hasbg   = (int)(pres & 1u);
        const int instnum = __popc(pres >> 1) + 1;

        // packed sorted order: 4 bits per position, low 8 in lo, high 8 in hi
        unsigned plo = 0u, phi = 0u;
        if (valid) {
            const int pos = pr[labcode] + __popc(b[labcode] & ((1u << lane) - 1u));
            if (pos < 8) plo = (unsigned)lane << (4 * pos);
            else         phi = (unsigned)lane << (4 * (pos - 8));
        }
        plo = __reduce_or_sync(0xffffffffu, plo);
        phi = __reduce_or_sync(0xffffffffu, phi);

        if (lane < NR) {
            s_start[warp][lane] = 0;
            s_end[warp][lane]   = 0;
            s_inv[warp][lane]   = 1.0f;
        }
        __syncwarp();
        if (lane < NR && cnt[lane] > 0) {
            const int r = (lane == 0) ? 0
                        : 1 + __popc((pres & ((1u << lane) - 1u)) >> 1);
            s_start[warp][r] = pr[lane];
            s_end[warp][r]   = pr[lane] + cnt[lane];
            s_inv[warp][r]   = 1.0f / (float)cnt[lane];
        }
        if (lane == 0) {
            s_instnum[warp] = instnum;
            s_hasbg[warp]   = hasbg;
            s_olo[warp]     = plo;
            s_ohi[warp]     = phi;
        }
    }

    // ----- stage features to smem (transposed [gs][s][c]) ----------------
    #pragma unroll
    for (int it = 0; it < 4; it++) {
        const int c  = dst_c[it];
        const int gs = dst_r[it] >> 2;
        const int q  = dst_r[it] & 3;
        float* d = s_sf + (gs * SS + q * 4) * CPAD + c;
        d[0 * CPAD] = v[it].x;
        d[1 * CPAD] = v[it].y;
        d[2 * CPAD] = v[it].z;
        d[3 * CPAD] = v[it].w;
    }
    __syncthreads();

    // ----- Phase B: per-channel instance means (segment gather) ----------
    {
        const int gs   = tid >> 7;        // 0..1
        const int c    = tid & (CC - 1);  // 0..127
        const int inum = s_instnum[gs];
        const unsigned long long ord =
            ((unsigned long long)s_ohi[gs] << 32) | s_olo[gs];
        const float* fcol = s_sf + gs * SS * CPAD + c;
        for (int r = 0; r < inum; r++) {
            const int st = s_start[gs][r];
            const int en = s_end[gs][r];
            float x = 0.0f;
            for (int k = st; k < en; k++) {
                const int smp = (int)((ord >> (4 * k)) & 15ull);
                x += fcol[smp * CPAD];
            }
            s_M[gs][r][c] = x * s_inv[gs][r];
        }
        if (!s_hasbg[gs])
            s_M[gs][0][c] = ctx_c;         // row 0 = context compensation
    }
    __syncthreads();

    // ----- Phase C: sim = (M M^T)/T — warp per pair (R10 proven form) ----
    {
        const int gs   = warp & 1;
        const int sub  = warp >> 1;         // 0..3
        const int inum = s_instnum[gs];
        const int P = inum * (inum + 1) / 2;   // <= 45
        for (int p = sub; p < P; p += 4) {
            const int i = TRI_I[p];
            const int j = TRI_J[p];
            const float4 a  = reinterpret_cast<const float4*>(s_M[gs][i])[lane];
            const float4 bb = reinterpret_cast<const float4*>(s_M[gs][j])[lane];
            float pa = a.x * bb.x + a.y * bb.y + a.z * bb.z + a.w * bb.w;
            #pragma unroll
            for (int o = 16; o; o >>= 1)
                pa += __shfl_xor_sync(0xffffffffu, pa, o);
            if (lane == 0) {
                const float x = pa * 5.0f;  // 1/T, T = 0.2
                s_sim[gs][i * NR + j] = x;
                s_sim[gs][j * NR + i] = x;
            }
        }
    }
    __syncthreads();

    // ----- Phase D: per-row logsumexp, group loss ------------------------
    if (warp < GP) {
        const int gs   = warp;
        const int inum = s_instnum[gs];
        float li = 0.0f;
        const int i = lane + 1;
        if (i < inum) {
            float mx = -3.402823466e38f;
            for (int j = 0; j < inum; j++)
                mx = fmaxf(mx, s_sim[gs][i * NR + j]);
            float sum = 0.0f;
            for (int j = 0; j < inum; j++)
                sum += __expf(s_sim[gs][i * NR + j] - mx);
            li = mx + __logf(sum) - s_sim[gs][i * NR + i];
        }
        #pragma unroll
        for (int o = 16; o; o >>= 1)
            li += __shfl_xor_sync(0xffffffffu, li, o);
        if (lane == 0) {
            const float gv = (inum >= 2) ? 1.0f : 0.0f;
            s_res[gs] = (inum >= 2) ? (li / (float)(inum - 1)) : 0.0f;
            s_gv[gs]  = gv;
        }
    }
    __syncthreads();

    if (tid == 0)
        g_part[blockIdx.x] = make_float2(s_res[0] + s_res[1],
                                         s_gv[0] + s_gv[1]);

#if __CUDA_ARCH__ >= 900
    cudaTriggerProgrammaticLaunchCompletion();
#endif
}

__global__ void __launch_bounds__(1024) proposal_clloss_reduce_kernel(
    float* __restrict__ out, int nCTA)
{
#if __CUDA_ARCH__ >= 900
    cudaGridDependencySynchronize();   // wait for group kernel's partials
#endif
    __shared__ float sn[32];
    __shared__ float sd[32];
    const int tid  = threadIdx.x;
    const int warp = tid >> 5;
    const int lane = tid & 31;

    const float4* p4 = reinterpret_cast<const float4*>(g_part);
    const int nq = nCTA >> 1;              // float4 count (nCTA even)
    float n = 0.0f, d = 0.0f;
    #pragma unroll 2
    for (int i = tid; i < nq; i += 1024) {
        const float4 x = p4[i];            // (gl0, gv0, gl1, gv1)
        n += x.x + x.z;
        d += x.y + x.w;
    }
    #pragma unroll
    for (int o = 16; o; o >>= 1) {
        n += __shfl_xor_sync(0xffffffffu, n, o);
        d += __shfl_xor_sync(0xffffffffu, d, o);
    }
    if (lane == 0) { sn[warp] = n; sd[warp] = d; }
    __syncthreads();
    if (warp == 0) {
        float nn = sn[lane];
        float dd = sd[lane];
        #pragma unroll
        for (int o = 16; o; o >>= 1) {
            nn += __shfl_xor_sync(0xffffffffu, nn, o);
            dd += __shfl_xor_sync(0xffffffffu, dd, o);
        }
        if (lane == 0) out[0] = nn / dd * 0.1f;
    }
}

extern "C" void kernel_launch(void* const* d_in, const int* in_sizes, int n_in,
                              void* d_out, int out_size)
{
    const int*   labs  = (const int*)  d_in[0];  // proposal_instance_mask [bs,Gn,S]
    const float* feats = (const float*)d_in[1];  // grouped_features [bs,C,Gn,S]
    const int*   idxs  = (const int*)  d_in[2];  // grouped_indices [bs,Gn,S]
    const float* ctx   = (const float*)d_in[3];  // context_compen [1,C]
    float*       out   = (float*)d_out;

    const int G = in_sizes[0] / SS;              // total group count (8192)
    const int nCTA = G / GP;

    proposal_clloss_group_kernel<<<nCTA, NTHR>>>(labs, feats, idxs, ctx);

    // PDL launch: overlap reduce-kernel setup with the group kernel's tail.
    cudaLaunchConfig_t cfg = {};
    cfg.gridDim  = dim3(1, 1, 1);
    cfg.blockDim = dim3(1024, 1, 1);
    cfg.dynamicSmemBytes = 0;
    cfg.stream = 0;                              // legacy default stream
    cudaLaunchAttribute attr[1];
    attr[0].id = cudaLaunchAttributeProgrammaticStreamSerialization;
    attr[0].val.programmaticStreamSerializationAllowed = 1;
    cfg.attrs = attr;
    cfg.numAttrs = 1;
    cudaLaunchKernelEx(&cfg, proposal_clloss_reduce_kernel, out, nCTA);
}